// round 13
// baseline (speedup 1.0000x reference)
#include <cuda_runtime.h>
#include <math.h>
#include <stdint.h>

// ---------------------------------------------------------------------------
// MultiHeadCrossAttentionBlock: B=4, S=2048, D=512, H=8, DK=64
// d_out = out [B,S,D] ++ attn.mean(axis=1) [B,S,S]
//
// Round 12 (resubmit of the round-10 recovery build; round-11 bench was an
// infra container failure, kernel never ran):
//  * k2 in the R8 structure (attn RMW batched in the softmax pass;
//    per-PV-chunk RMW measured +100us in R9). Softmax pass float4-vectorized.
//  * k3 || k5 stream fork (dependency-free overlap; capture-legal, ran in R9).
//  * k5 at 64x128 FFMA2 (measured equal to 128x128, higher occupancy).
// ---------------------------------------------------------------------------

namespace cfg {
constexpr int B  = 4;
constexpr int S  = 2048;
constexpr int D  = 512;
constexpr int H  = 8;
constexpr int DK = 64;
constexpr int N3 = 3 * D;          // 1536
constexpr int MROWS = B * S;       // 8192
constexpr float SCALE = 0.125f;
constexpr int TQ = 16;
constexpr int TK = 256;            // QK k-chunk
constexpr int NCH = S / TK;        // 8
constexpr int VCH = 128;           // PV k-chunk (double-buffered)
constexpr int NVC = S / VCH;       // 16
constexpr int SROW = S + 4;
constexpr int SMEM2_FLOATS = TQ * SROW + DK * TK + DK * 20 + 64;
constexpr int SMEM2 = SMEM2_FLOATS * 4;
constexpr int HGRP = H / 2;
}

// ------------------------------ scratch ------------------------------------
__device__ float g_Q [cfg::B * cfg::H * cfg::S * cfg::DK];
__device__ float g_Kt[cfg::B * cfg::H * cfg::DK * cfg::S];
__device__ float g_V [cfg::B * cfg::H * cfg::S * cfg::DK];
__device__ float g_ctx[cfg::B * cfg::S * cfg::D];
__device__ float g_attn2[(size_t)cfg::B * cfg::S * cfg::S];

// ---------------------------------------------------------------------------
// packed f32x2 helpers (k5 only)
// ---------------------------------------------------------------------------
__device__ __forceinline__ void ffma2(unsigned long long& d,
                                      unsigned long long a,
                                      unsigned long long b) {
    asm("fma.rn.f32x2 %0, %1, %2, %0;" : "+l"(d) : "l"(a), "l"(b));
}
__device__ __forceinline__ unsigned long long pack2(float x) {
    unsigned long long r;
    asm("mov.b64 %0, {%1, %1};" : "=l"(r) : "f"(x));
    return r;
}
__device__ __forceinline__ float2 unpack2(unsigned long long v) {
    float lo, hi;
    asm("mov.b64 {%0, %1}, %2;" : "=f"(lo), "=f"(hi) : "l"(v));
    return make_float2(lo, hi);
}

// ---------------------------------------------------------------------------
// K1: QKV projection (plain FFMA; at the fp32 roof)
// ---------------------------------------------------------------------------
__global__ __launch_bounds__(256) void k1_qkv(
    const float* __restrict__ Zq, const float* __restrict__ Zkv,
    const float* __restrict__ W)
{
    using namespace cfg;
    constexpr int BM = 128, BN = 128, BK = 16;
    __shared__ float As[BK][BM + 4];
    __shared__ float Bs[BK][BN];

    const int row0 = blockIdx.x * BM;
    const int col0 = blockIdx.y * BN;
    const float* __restrict__ Z = (col0 < D) ? Zq : Zkv;

    const int t  = threadIdx.x;
    const int tm = (t >> 4) << 3;
    const int tn = (t & 15) << 3;

    float acc[8][8];
#pragma unroll
    for (int i = 0; i < 8; i++)
#pragma unroll
        for (int j = 0; j < 8; j++) acc[i][j] = 0.f;

    for (int k0 = 0; k0 < D; k0 += BK) {
#pragma unroll
        for (int i = 0; i < 8; i++) {
            int p = t + i * 256;
            int m = p >> 4, k = p & 15;
            As[k][m] = Z[(size_t)(row0 + m) * D + k0 + k];
        }
#pragma unroll
        for (int i = 0; i < 8; i++) {
            int p = t + i * 256;
            int k = p >> 7, n = p & 127;
            Bs[k][n] = W[(size_t)(k0 + k) * N3 + col0 + n];
        }
        __syncthreads();
#pragma unroll
        for (int k = 0; k < BK; k++) {
            float a[8], b[8];
#pragma unroll
            for (int i = 0; i < 8; i++) a[i] = As[k][tm + i];
#pragma unroll
            for (int j = 0; j < 8; j++) b[j] = Bs[k][tn + j];
#pragma unroll
            for (int i = 0; i < 8; i++)
#pragma unroll
                for (int j = 0; j < 8; j++)
                    acc[i][j] = fmaf(a[i], b[j], acc[i][j]);
        }
        __syncthreads();
    }

    const int part = col0 / D;
#pragma unroll
    for (int i = 0; i < 8; i++) {
        const int r = row0 + tm + i;
        const int b = r >> 11, s = r & (S - 1);
#pragma unroll
        for (int j = 0; j < 8; j++) {
            const int c  = col0 + tn + j - part * D;
            const int h  = c >> 6, dk = c & 63;
            const float v = acc[i][j];
            if (part == 0)      g_Q [((size_t)(b * H + h) * S  + s)  * DK + dk] = v;
            else if (part == 1) g_Kt[((size_t)(b * H + h) * DK + dk) * S  + s ] = v;
            else                g_V [((size_t)(b * H + h) * S  + s)  * DK + dk] = v;
        }
    }
}

// ---------------------------------------------------------------------------
// K2: fused attention (R8 structure; float4 softmax pass).
// ---------------------------------------------------------------------------
__global__ __launch_bounds__(256, 1) void k2_attn(
    const float* __restrict__ mask, float* __restrict__ attn_out)
{
    using namespace cfg;
    extern __shared__ float sm[];
    float* Ss  = sm;                       // scores / raw exp values
    float* KVs = Ss + TQ * SROW;           // QK: [64][256]; PV: 2 x [128][64]
    float* Qs  = KVs + DK * TK;            // [64][20]
    float* Rb  = Qs + DK * 20;             // 32: row maxes
    float* Lb  = Rb + 32;                  // 16: 1/l per row

    const int qt = blockIdx.x;
    const int b  = blockIdx.y;
    const int hz = blockIdx.z;
    const int h0 = hz * HGRP;
    const int q0 = qt * TQ;
    const int t  = threadIdx.x;

    float* __restrict__ attn_dst = (hz == 0) ? attn_out : g_attn2;

    const int qi = t >> 6;
    const int ki = t & 63;
    const int qg4 = ((t >> 4) & 3) << 2;
    const int cg4 = (t & 15) << 2;
    const int w = t >> 5, lane = t & 31;

    float4 pf[16];

    for (int hh = 0; hh < HGRP; hh++) {
        const int h  = h0 + hh;
        const int bh = b * H + h;
        const float* __restrict__ Qg  = g_Q  + ((size_t)bh * S + q0) * DK;
        const float* __restrict__ Ktg = g_Kt + (size_t)bh * DK * S;
        const float* __restrict__ Vg  = g_V  + (size_t)bh * S * DK;

#pragma unroll
        for (int i = 0; i < 4; i++) {
            int p = t + i * 256;
            Qs[(p & 63) * 20 + (p >> 6)] = Qg[(p >> 6) * DK + (p & 63)];
        }
#pragma unroll
        for (int i = 0; i < 16; i++) {
            int p4 = t + (i << 8);
            pf[i] = *(const float4*)&Ktg[(size_t)(p4 >> 6) * S + ((p4 & 63) << 2)];
        }
        __syncthreads();
#pragma unroll
        for (int i = 0; i < 8; i++) {
            int p4 = t + (i << 8);
            *(float4*)&KVs[(p4 >> 6) * TK + ((p4 & 63) << 2)] = pf[i];
        }

        float rmax[4] = {-1e30f, -1e30f, -1e30f, -1e30f};

        // ================= QK^T: 8 chunks, d-half pipelined =================
        for (int c = 0; c < NCH; c++) {
            __syncthreads();
#pragma unroll
            for (int i = 8; i < 16; i++) {
                int p4 = t + (i << 8);
                *(float4*)&KVs[(p4 >> 6) * TK + ((p4 & 63) << 2)] = pf[i];
            }

            float acc[4][4];
#pragma unroll
            for (int i = 0; i < 4; i++)
#pragma unroll
                for (int j = 0; j < 4; j++) acc[i][j] = 0.f;

#pragma unroll
            for (int d = 0; d < 32; d++) {
                const float4 kv = *(const float4*)&KVs[d * TK + (ki << 2)];
                const float4 qv = *(const float4*)&Qs[d * 20 + (qi << 2)];
                acc[0][0] = fmaf(qv.x, kv.x, acc[0][0]);
                acc[0][1] = fmaf(qv.x, kv.y, acc[0][1]);
                acc[0][2] = fmaf(qv.x, kv.z, acc[0][2]);
                acc[0][3] = fmaf(qv.x, kv.w, acc[0][3]);
                acc[1][0] = fmaf(qv.y, kv.x, acc[1][0]);
                acc[1][1] = fmaf(qv.y, kv.y, acc[1][1]);
                acc[1][2] = fmaf(qv.y, kv.z, acc[1][2]);
                acc[1][3] = fmaf(qv.y, kv.w, acc[1][3]);
                acc[2][0] = fmaf(qv.z, kv.x, acc[2][0]);
                acc[2][1] = fmaf(qv.z, kv.y, acc[2][1]);
                acc[2][2] = fmaf(qv.z, kv.z, acc[2][2]);
                acc[2][3] = fmaf(qv.z, kv.w, acc[2][3]);
                acc[3][0] = fmaf(qv.w, kv.x, acc[3][0]);
                acc[3][1] = fmaf(qv.w, kv.y, acc[3][1]);
                acc[3][2] = fmaf(qv.w, kv.z, acc[3][2]);
                acc[3][3] = fmaf(qv.w, kv.w, acc[3][3]);
            }

            if (c < NCH - 1) {
#pragma unroll
                for (int i = 0; i < 16; i++) {
                    int p4 = t + (i << 8);
                    pf[i] = *(const float4*)&Ktg[(size_t)(p4 >> 6) * S + (c + 1) * TK + ((p4 & 63) << 2)];
                }
            } else {
#pragma unroll
                for (int i = 0; i < 8; i++) {
                    int p4 = t + (i << 8);
                    pf[i] = *(const float4*)&Vg[(size_t)(p4 >> 4) * DK + ((p4 & 15) << 2)];
                }
            }

            __syncthreads();
            if (c < NCH - 1) {
#pragma unroll
                for (int i = 0; i < 8; i++) {
                    int p4 = t + (i << 8);
                    *(float4*)&KVs[(p4 >> 6) * TK + ((p4 & 63) << 2)] = pf[i];
                }
            }

#pragma unroll
            for (int d = 32; d < 64; d++) {
                const float4 kv = *(const float4*)&KVs[d * TK + (ki << 2)];
                const float4 qv = *(const float4*)&Qs[d * 20 + (qi << 2)];
                acc[0][0] = fmaf(qv.x, kv.x, acc[0][0]);
                acc[0][1] = fmaf(qv.x, kv.y, acc[0][1]);
                acc[0][2] = fmaf(qv.x, kv.z, acc[0][2]);
                acc[0][3] = fmaf(qv.x, kv.w, acc[0][3]);
                acc[1][0] = fmaf(qv.y, kv.x, acc[1][0]);
                acc[1][1] = fmaf(qv.y, kv.y, acc[1][1]);
                acc[1][2] = fmaf(qv.y, kv.z, acc[1][2]);
                acc[1][3] = fmaf(qv.y, kv.w, acc[1][3]);
                acc[2][0] = fmaf(qv.z, kv.x, acc[2][0]);
                acc[2][1] = fmaf(qv.z, kv.y, acc[2][1]);
                acc[2][2] = fmaf(qv.z, kv.z, acc[2][2]);
                acc[2][3] = fmaf(qv.z, kv.w, acc[2][3]);
                acc[3][0] = fmaf(qv.w, kv.x, acc[3][0]);
                acc[3][1] = fmaf(qv.w, kv.y, acc[3][1]);
                acc[3][2] = fmaf(qv.w, kv.z, acc[3][2]);
                acc[3][3] = fmaf(qv.w, kv.w, acc[3][3]);
            }

#pragma unroll
            for (int i = 0; i < 4; i++) {
                const int q = (qi << 2) + i;
                const float4 mk = *(const float4*)&mask[(size_t)(q0 + q) * S + c * TK + (ki << 2)];
                float4 o;
                o.x = fmaf(acc[i][0], SCALE, mk.x);
                o.y = fmaf(acc[i][1], SCALE, mk.y);
                o.z = fmaf(acc[i][2], SCALE, mk.z);
                o.w = fmaf(acc[i][3], SCALE, mk.w);
                *(float4*)&Ss[q * SROW + c * TK + (ki << 2)] = o;
                rmax[i] = fmaxf(rmax[i], fmaxf(fmaxf(o.x, o.y), fmaxf(o.z, o.w)));
            }
        }

        // ---- row-max reduce ----
#pragma unroll
        for (int j = 0; j < 4; j++) {
            float m = rmax[j];
#pragma unroll
            for (int o = 16; o; o >>= 1) m = fmaxf(m, __shfl_xor_sync(0xFFFFFFFFu, m, o));
            rmax[j] = m;
        }
        if (lane == 0) {
#pragma unroll
            for (int j = 0; j < 4; j++) Rb[qi * 8 + (w & 1) * 4 + j] = rmax[j];
        }
        __syncthreads();

        // stage V chunk 0; prefetch V chunk 1
#pragma unroll
        for (int i = 0; i < 8; i++) {
            int p4 = t + (i << 8);
            *(float4*)&KVs[(p4 >> 4) * DK + ((p4 & 15) << 2)] = pf[i];
        }
#pragma unroll
        for (int i = 0; i < 8; i++) {
            int p4 = t + (i << 8);
            pf[i] = *(const float4*)&Vg[(size_t)(VCH + (p4 >> 4)) * DK + ((p4 & 15) << 2)];
        }

        // ---- softmax + batched attn RMW (float4 vectorized) ----
#pragma unroll
        for (int rr = 0; rr < 2; rr++) {
            const int q = w * 2 + rr;
            float* row = Ss + q * SROW;
            const float m = fmaxf(Rb[(q >> 2) * 8 + (q & 3)],
                                  Rb[(q >> 2) * 8 + 4 + (q & 3)]);
            float l0 = 0.f, l1 = 0.f, l2 = 0.f, l3 = 0.f;
            for (int i = lane * 4; i < S; i += 128) {
                float4 e = *(float4*)&row[i];
                e.x = __expf(e.x - m); e.y = __expf(e.y - m);
                e.z = __expf(e.z - m); e.w = __expf(e.w - m);
                *(float4*)&row[i] = e;                 // raw exp stays in smem
                l0 += e.x; l1 += e.y; l2 += e.z; l3 += e.w;
            }
            float l = (l0 + l1) + (l2 + l3);
#pragma unroll
            for (int o = 16; o; o >>= 1) l += __shfl_xor_sync(0xFFFFFFFFu, l, o);
            const float inv = 1.f / l;
            if (lane == 0) Lb[q] = inv;
            const float invk = inv * 0.125f;

            float* __restrict__ arow = attn_dst + ((size_t)b * S + q0 + q) * S;
            for (int i = lane * 4; i < S; i += 128) {
                float4 e = *(float4*)&row[i];
                float4 a;
                a.x = e.x * invk; a.y = e.y * invk;
                a.z = e.z * invk; a.w = e.w * invk;
                if (hh > 0) {
                    float4 prev = *(float4*)&arow[i];
                    a.x += prev.x; a.y += prev.y; a.z += prev.z; a.w += prev.w;
                }
                *(float4*)&arow[i] = a;
            }
        }
        __syncthreads();                   // V buf0 + Lb + exp values visible

        // ================= PV: 16 chunks of 128 rows, double-buffered =======
        float4 cacc[4];
#pragma unroll
        for (int i = 0; i < 4; i++) cacc[i] = make_float4(0.f, 0.f, 0.f, 0.f);

        const int rb = qi << 5;
        for (int c = 0; c < NVC; c++) {
            const float* buf = KVs + (c & 1) * 8192;
            if (c < NVC - 1) {
                float* nbuf = KVs + ((c + 1) & 1) * 8192;
#pragma unroll
                for (int i = 0; i < 8; i++) {
                    int p4 = t + (i << 8);
                    *(float4*)&nbuf[(p4 >> 4) * DK + ((p4 & 15) << 2)] = pf[i];
                }
            }
            if (c < NVC - 2) {
#pragma unroll
                for (int i = 0; i < 8; i++) {
                    int p4 = t + (i << 8);
                    pf[i] = *(const float4*)&Vg[(size_t)((c + 2) * VCH + (p4 >> 4)) * DK + ((p4 & 15) << 2)];
                }
            }
#pragma unroll
            for (int kk = 0; kk < 32; kk += 4) {
                const float4 v0 = *(const float4*)&buf[(rb + kk + 0) * DK + cg4];
                const float4 v1 = *(const float4*)&buf[(rb + kk + 1) * DK + cg4];
                const float4 v2 = *(const float4*)&buf[(rb + kk + 2) * DK + cg4];
                const float4 v3 = *(const float4*)&buf[(rb + kk + 3) * DK + cg4];
#pragma unroll
                for (int i = 0; i < 4; i++) {
                    const float4 p = *(const float4*)&Ss[(qg4 + i) * SROW + c * VCH + rb + kk];
                    cacc[i].x = fmaf(p.x, v0.x, cacc[i].x);
                    cacc[i].y = fmaf(p.x, v0.y, cacc[i].y);
                    cacc[i].z = fmaf(p.x, v0.z, cacc[i].z);
                    cacc[i].w = fmaf(p.x, v0.w, cacc[i].w);
                    cacc[i].x = fmaf(p.y, v1.x, cacc[i].x);
                    cacc[i].y = fmaf(p.y, v1.y, cacc[i].y);
                    cacc[i].z = fmaf(p.y, v1.z, cacc[i].z);
                    cacc[i].w = fmaf(p.y, v1.w, cacc[i].w);
                    cacc[i].x = fmaf(p.z, v2.x, cacc[i].x);
                    cacc[i].y = fmaf(p.z, v2.y, cacc[i].y);
                    cacc[i].z = fmaf(p.z, v2.z, cacc[i].z);
                    cacc[i].w = fmaf(p.z, v2.w, cacc[i].w);
                    cacc[i].x = fmaf(p.w, v3.x, cacc[i].x);
                    cacc[i].y = fmaf(p.w, v3.y, cacc[i].y);
                    cacc[i].z = fmaf(p.w, v3.z, cacc[i].z);
                    cacc[i].w = fmaf(p.w, v3.w, cacc[i].w);
                }
            }
            __syncthreads();
        }

        // ---- deferred normalization + partial reduce ----
#pragma unroll
        for (int i = 0; i < 4; i++) {
            const float f = Lb[qg4 + i];
            cacc[i].x *= f; cacc[i].y *= f; cacc[i].z *= f; cacc[i].w *= f;
        }
#pragma unroll
        for (int i = 0; i < 4; i++)
            *(float4*)&KVs[(qi << 10) + (qg4 + i) * DK + cg4] = cacc[i];
        __syncthreads();
        {
            const int q  = t >> 4;
            const int c4 = (t & 15) << 2;
            float4 s0 = *(const float4*)&KVs[0 * 1024 + q * DK + c4];
            float4 s1 = *(const float4*)&KVs[1 * 1024 + q * DK + c4];
            float4 s2 = *(const float4*)&KVs[2 * 1024 + q * DK + c4];
            float4 s3 = *(const float4*)&KVs[3 * 1024 + q * DK + c4];
            float4 o;
            o.x = (s0.x + s1.x) + (s2.x + s3.x);
            o.y = (s0.y + s1.y) + (s2.y + s3.y);
            o.z = (s0.z + s1.z) + (s2.z + s3.z);
            o.w = (s0.w + s1.w) + (s2.w + s3.w);
            *(float4*)&g_ctx[((size_t)b * S + q0 + q) * D + h * DK + c4] = o;
        }
    }
}

// ---------------------------------------------------------------------------
// K3: attn_out += g_attn2
// ---------------------------------------------------------------------------
__global__ __launch_bounds__(256) void k3_merge(float* __restrict__ attn_out)
{
    using namespace cfg;
    const size_t i4 = (size_t)blockIdx.x * 256 + threadIdx.x;
    float4 a = ((const float4*)g_attn2)[i4];
    float4 o = ((float4*)attn_out)[i4];
    o.x += a.x; o.y += a.y; o.z += a.z; o.w += a.w;
    ((float4*)attn_out)[i4] = o;
}

// ---------------------------------------------------------------------------
// K5: out = ctx @ Wout. 64x128 tiles, FFMA2 inner.
// ---------------------------------------------------------------------------
__global__ __launch_bounds__(256) void k5_out(
    const float* __restrict__ Wout, float* __restrict__ out)
{
    using namespace cfg;
    constexpr int BM = 64, BN = 128, BK = 16;
    __shared__ float As[BK][BM + 4];
    __shared__ float Bs[BK][BN];

    const int row0 = blockIdx.x * BM;
    const int col0 = blockIdx.y * BN;
    const int t  = threadIdx.x;
    const int tm = (t >> 5) << 3;
    const int tn = (t & 31) << 2;

    unsigned long long acc2[8][2];
#pragma unroll
    for (int i = 0; i < 8; i++) { acc2[i][0] = 0ULL; acc2[i][1] = 0ULL; }

    for (int k0 = 0; k0 < D; k0 += BK) {
#pragma unroll
        for (int i = 0; i < 4; i++) {
            int p = t + i * 256;
            int m = p >> 4, k = p & 15;
            As[k][m] = g_ctx[(size_t)(row0 + m) * D + k0 + k];
        }
#pragma unroll
        for (int i = 0; i < 8; i++) {
            int p = t + i * 256;
            int k = p >> 7, n = p & 127;
            Bs[k][n] = Wout[(size_t)(k0 + k) * D + col0 + n];
        }
        __syncthreads();
#pragma unroll
        for (int k = 0; k < BK; k++) {
            const ulonglong2 bb = *(const ulonglong2*)&Bs[k][tn];
            float a[8];
#pragma unroll
            for (int i = 0; i < 8; i++) a[i] = As[k][tm + i];
#pragma unroll
            for (int i = 0; i < 8; i++) {
                const unsigned long long aa = pack2(a[i]);
                ffma2(acc2[i][0], aa, bb.x);
                ffma2(acc2[i][1], aa, bb.y);
            }
        }
        __syncthreads();
    }
#pragma unroll
    for (int i = 0; i < 8; i++) {
        const int r = row0 + tm + i;
        const float2 v0 = unpack2(acc2[i][0]);
        const float2 v1 = unpack2(acc2[i][1]);
        *(float4*)&out[(size_t)r * D + col0 + tn] =
            make_float4(v0.x, v0.y, v1.x, v1.y);
    }
}

// ---------------------------------------------------------------------------
namespace {
cudaStream_t g_side = nullptr;
cudaEvent_t  g_evFork = nullptr, g_evJoin = nullptr;
struct CudaWarm {
    CudaWarm() {
        cudaFuncSetAttribute(k2_attn,
            cudaFuncAttributeMaxDynamicSharedMemorySize, cfg::SMEM2);
        cudaStreamCreateWithFlags(&g_side, cudaStreamNonBlocking);
        cudaEventCreateWithFlags(&g_evFork, cudaEventDisableTiming);
        cudaEventCreateWithFlags(&g_evJoin, cudaEventDisableTiming);
        cudaFuncAttributes a;
        cudaFuncGetAttributes(&a, (const void*)k1_qkv);
        cudaFuncGetAttributes(&a, (const void*)k2_attn);
        cudaFuncGetAttributes(&a, (const void*)k3_merge);
        cudaFuncGetAttributes(&a, (const void*)k5_out);
    }
};
CudaWarm g_warm;
}

// ---------------------------------------------------------------------------
extern "C" void kernel_launch(void* const* d_in, const int* in_sizes, int n_in,
                              void* d_out, int out_size)
{
    using namespace cfg;
    const float* Zq   = (const float*)d_in[0];
    const float* Zkv  = (const float*)d_in[1];
    const float* mask = (const float*)d_in[2];
    const float* Wqkv = (const float*)d_in[3];
    const float* Wout = (const float*)d_in[4];

    float* out       = (float*)d_out;
    float* attn_mean = out + (size_t)B * S * D;

    cudaFuncSetAttribute(k2_attn,
        cudaFuncAttributeMaxDynamicSharedMemorySize, SMEM2);

    k1_qkv<<<dim3(MROWS / 128, N3 / 128), 256>>>(Zq, Zkv, Wqkv);
    k2_attn<<<dim3(S / TQ, B, 2), 256, SMEM2>>>(mask, attn_mean);

    const int mergeBlocks = (int)((size_t)B * S * S / 4 / 256);
    if (g_side && g_evFork && g_evJoin) {
        cudaEventRecord(g_evFork, 0);
        cudaStreamWaitEvent(g_side, g_evFork, 0);
        k3_merge<<<mergeBlocks, 256, 0, g_side>>>(attn_mean);
        k5_out<<<dim3(MROWS / 64, D / 128), 256>>>(Wout, out);
        cudaEventRecord(g_evJoin, g_side);
        cudaStreamWaitEvent(0, g_evJoin, 0);
    } else {
        k3_merge<<<mergeBlocks, 256>>>(attn_mean);
        k5_out<<<dim3(MROWS / 64, D / 128), 256>>>(Wout, out);
    }
}

// round 14
// speedup vs baseline: 1.5858x; 1.5858x over previous
#include <cuda_runtime.h>
#include <math.h>
#include <stdint.h>

// ---------------------------------------------------------------------------
// MultiHeadCrossAttentionBlock: B=4, S=2048, D=512, H=8, DK=64
// d_out = out [B,S,D] ++ attn.mean(axis=1) [B,S,S]
//
// Round 13: byte-identical resubmit of the round-12 build. R12's container
// was ~1.6x down-clocked (k5 114->184us on identical code; HBM 156->97GB/s;
// whole run scales by the same factor to ~1790us). Need a clean-clock
// measurement of this build before changing anything.
//  * k2: R8 structure (attn RMW batched in softmax pass), float4 softmax.
//  * k3 || k5 stream fork (dependency-free overlap).
//  * k5: 64x128 FFMA2 (measured 114us on a healthy container in R10).
// ---------------------------------------------------------------------------

namespace cfg {
constexpr int B  = 4;
constexpr int S  = 2048;
constexpr int D  = 512;
constexpr int H  = 8;
constexpr int DK = 64;
constexpr int N3 = 3 * D;          // 1536
constexpr int MROWS = B * S;       // 8192
constexpr float SCALE = 0.125f;
constexpr int TQ = 16;
constexpr int TK = 256;            // QK k-chunk
constexpr int NCH = S / TK;        // 8
constexpr int VCH = 128;           // PV k-chunk (double-buffered)
constexpr int NVC = S / VCH;       // 16
constexpr int SROW = S + 4;
constexpr int SMEM2_FLOATS = TQ * SROW + DK * TK + DK * 20 + 64;
constexpr int SMEM2 = SMEM2_FLOATS * 4;
constexpr int HGRP = H / 2;
}

// ------------------------------ scratch ------------------------------------
__device__ float g_Q [cfg::B * cfg::H * cfg::S * cfg::DK];
__device__ float g_Kt[cfg::B * cfg::H * cfg::DK * cfg::S];
__device__ float g_V [cfg::B * cfg::H * cfg::S * cfg::DK];
__device__ float g_ctx[cfg::B * cfg::S * cfg::D];
__device__ float g_attn2[(size_t)cfg::B * cfg::S * cfg::S];

// ---------------------------------------------------------------------------
// packed f32x2 helpers (k5 only)
// ---------------------------------------------------------------------------
__device__ __forceinline__ void ffma2(unsigned long long& d,
                                      unsigned long long a,
                                      unsigned long long b) {
    asm("fma.rn.f32x2 %0, %1, %2, %0;" : "+l"(d) : "l"(a), "l"(b));
}
__device__ __forceinline__ unsigned long long pack2(float x) {
    unsigned long long r;
    asm("mov.b64 %0, {%1, %1};" : "=l"(r) : "f"(x));
    return r;
}
__device__ __forceinline__ float2 unpack2(unsigned long long v) {
    float lo, hi;
    asm("mov.b64 {%0, %1}, %2;" : "=f"(lo), "=f"(hi) : "l"(v));
    return make_float2(lo, hi);
}

// ---------------------------------------------------------------------------
// K1: QKV projection (plain FFMA; at the fp32 roof)
// ---------------------------------------------------------------------------
__global__ __launch_bounds__(256) void k1_qkv(
    const float* __restrict__ Zq, const float* __restrict__ Zkv,
    const float* __restrict__ W)
{
    using namespace cfg;
    constexpr int BM = 128, BN = 128, BK = 16;
    __shared__ float As[BK][BM + 4];
    __shared__ float Bs[BK][BN];

    const int row0 = blockIdx.x * BM;
    const int col0 = blockIdx.y * BN;
    const float* __restrict__ Z = (col0 < D) ? Zq : Zkv;

    const int t  = threadIdx.x;
    const int tm = (t >> 4) << 3;
    const int tn = (t & 15) << 3;

    float acc[8][8];
#pragma unroll
    for (int i = 0; i < 8; i++)
#pragma unroll
        for (int j = 0; j < 8; j++) acc[i][j] = 0.f;

    for (int k0 = 0; k0 < D; k0 += BK) {
#pragma unroll
        for (int i = 0; i < 8; i++) {
            int p = t + i * 256;
            int m = p >> 4, k = p & 15;
            As[k][m] = Z[(size_t)(row0 + m) * D + k0 + k];
        }
#pragma unroll
        for (int i = 0; i < 8; i++) {
            int p = t + i * 256;
            int k = p >> 7, n = p & 127;
            Bs[k][n] = W[(size_t)(k0 + k) * N3 + col0 + n];
        }
        __syncthreads();
#pragma unroll
        for (int k = 0; k < BK; k++) {
            float a[8], b[8];
#pragma unroll
            for (int i = 0; i < 8; i++) a[i] = As[k][tm + i];
#pragma unroll
            for (int j = 0; j < 8; j++) b[j] = Bs[k][tn + j];
#pragma unroll
            for (int i = 0; i < 8; i++)
#pragma unroll
                for (int j = 0; j < 8; j++)
                    acc[i][j] = fmaf(a[i], b[j], acc[i][j]);
        }
        __syncthreads();
    }

    const int part = col0 / D;
#pragma unroll
    for (int i = 0; i < 8; i++) {
        const int r = row0 + tm + i;
        const int b = r >> 11, s = r & (S - 1);
#pragma unroll
        for (int j = 0; j < 8; j++) {
            const int c  = col0 + tn + j - part * D;
            const int h  = c >> 6, dk = c & 63;
            const float v = acc[i][j];
            if (part == 0)      g_Q [((size_t)(b * H + h) * S  + s)  * DK + dk] = v;
            else if (part == 1) g_Kt[((size_t)(b * H + h) * DK + dk) * S  + s ] = v;
            else                g_V [((size_t)(b * H + h) * S  + s)  * DK + dk] = v;
        }
    }
}

// ---------------------------------------------------------------------------
// K2: fused attention (R8 structure; float4 softmax pass).
// ---------------------------------------------------------------------------
__global__ __launch_bounds__(256, 1) void k2_attn(
    const float* __restrict__ mask, float* __restrict__ attn_out)
{
    using namespace cfg;
    extern __shared__ float sm[];
    float* Ss  = sm;                       // scores / raw exp values
    float* KVs = Ss + TQ * SROW;           // QK: [64][256]; PV: 2 x [128][64]
    float* Qs  = KVs + DK * TK;            // [64][20]
    float* Rb  = Qs + DK * 20;             // 32: row maxes
    float* Lb  = Rb + 32;                  // 16: 1/l per row

    const int qt = blockIdx.x;
    const int b  = blockIdx.y;
    const int hz = blockIdx.z;
    const int h0 = hz * HGRP;
    const int q0 = qt * TQ;
    const int t  = threadIdx.x;

    float* __restrict__ attn_dst = (hz == 0) ? attn_out : g_attn2;

    const int qi = t >> 6;
    const int ki = t & 63;
    const int qg4 = ((t >> 4) & 3) << 2;
    const int cg4 = (t & 15) << 2;
    const int w = t >> 5, lane = t & 31;

    float4 pf[16];

    for (int hh = 0; hh < HGRP; hh++) {
        const int h  = h0 + hh;
        const int bh = b * H + h;
        const float* __restrict__ Qg  = g_Q  + ((size_t)bh * S + q0) * DK;
        const float* __restrict__ Ktg = g_Kt + (size_t)bh * DK * S;
        const float* __restrict__ Vg  = g_V  + (size_t)bh * S * DK;

#pragma unroll
        for (int i = 0; i < 4; i++) {
            int p = t + i * 256;
            Qs[(p & 63) * 20 + (p >> 6)] = Qg[(p >> 6) * DK + (p & 63)];
        }
#pragma unroll
        for (int i = 0; i < 16; i++) {
            int p4 = t + (i << 8);
            pf[i] = *(const float4*)&Ktg[(size_t)(p4 >> 6) * S + ((p4 & 63) << 2)];
        }
        __syncthreads();
#pragma unroll
        for (int i = 0; i < 8; i++) {
            int p4 = t + (i << 8);
            *(float4*)&KVs[(p4 >> 6) * TK + ((p4 & 63) << 2)] = pf[i];
        }

        float rmax[4] = {-1e30f, -1e30f, -1e30f, -1e30f};

        // ================= QK^T: 8 chunks, d-half pipelined =================
        for (int c = 0; c < NCH; c++) {
            __syncthreads();
#pragma unroll
            for (int i = 8; i < 16; i++) {
                int p4 = t + (i << 8);
                *(float4*)&KVs[(p4 >> 6) * TK + ((p4 & 63) << 2)] = pf[i];
            }

            float acc[4][4];
#pragma unroll
            for (int i = 0; i < 4; i++)
#pragma unroll
                for (int j = 0; j < 4; j++) acc[i][j] = 0.f;

#pragma unroll
            for (int d = 0; d < 32; d++) {
                const float4 kv = *(const float4*)&KVs[d * TK + (ki << 2)];
                const float4 qv = *(const float4*)&Qs[d * 20 + (qi << 2)];
                acc[0][0] = fmaf(qv.x, kv.x, acc[0][0]);
                acc[0][1] = fmaf(qv.x, kv.y, acc[0][1]);
                acc[0][2] = fmaf(qv.x, kv.z, acc[0][2]);
                acc[0][3] = fmaf(qv.x, kv.w, acc[0][3]);
                acc[1][0] = fmaf(qv.y, kv.x, acc[1][0]);
                acc[1][1] = fmaf(qv.y, kv.y, acc[1][1]);
                acc[1][2] = fmaf(qv.y, kv.z, acc[1][2]);
                acc[1][3] = fmaf(qv.y, kv.w, acc[1][3]);
                acc[2][0] = fmaf(qv.z, kv.x, acc[2][0]);
                acc[2][1] = fmaf(qv.z, kv.y, acc[2][1]);
                acc[2][2] = fmaf(qv.z, kv.z, acc[2][2]);
                acc[2][3] = fmaf(qv.z, kv.w, acc[2][3]);
                acc[3][0] = fmaf(qv.w, kv.x, acc[3][0]);
                acc[3][1] = fmaf(qv.w, kv.y, acc[3][1]);
                acc[3][2] = fmaf(qv.w, kv.z, acc[3][2]);
                acc[3][3] = fmaf(qv.w, kv.w, acc[3][3]);
            }

            if (c < NCH - 1) {
#pragma unroll
                for (int i = 0; i < 16; i++) {
                    int p4 = t + (i << 8);
                    pf[i] = *(const float4*)&Ktg[(size_t)(p4 >> 6) * S + (c + 1) * TK + ((p4 & 63) << 2)];
                }
            } else {
#pragma unroll
                for (int i = 0; i < 8; i++) {
                    int p4 = t + (i << 8);
                    pf[i] = *(const float4*)&Vg[(size_t)(p4 >> 4) * DK + ((p4 & 15) << 2)];
                }
            }

            __syncthreads();
            if (c < NCH - 1) {
#pragma unroll
                for (int i = 0; i < 8; i++) {
                    int p4 = t + (i << 8);
                    *(float4*)&KVs[(p4 >> 6) * TK + ((p4 & 63) << 2)] = pf[i];
                }
            }

#pragma unroll
            for (int d = 32; d < 64; d++) {
                const float4 kv = *(const float4*)&KVs[d * TK + (ki << 2)];
                const float4 qv = *(const float4*)&Qs[d * 20 + (qi << 2)];
                acc[0][0] = fmaf(qv.x, kv.x, acc[0][0]);
                acc[0][1] = fmaf(qv.x, kv.y, acc[0][1]);
                acc[0][2] = fmaf(qv.x, kv.z, acc[0][2]);
                acc[0][3] = fmaf(qv.x, kv.w, acc[0][3]);
                acc[1][0] = fmaf(qv.y, kv.x, acc[1][0]);
                acc[1][1] = fmaf(qv.y, kv.y, acc[1][1]);
                acc[1][2] = fmaf(qv.y, kv.z, acc[1][2]);
                acc[1][3] = fmaf(qv.y, kv.w, acc[1][3]);
                acc[2][0] = fmaf(qv.z, kv.x, acc[2][0]);
                acc[2][1] = fmaf(qv.z, kv.y, acc[2][1]);
                acc[2][2] = fmaf(qv.z, kv.z, acc[2][2]);
                acc[2][3] = fmaf(qv.z, kv.w, acc[2][3]);
                acc[3][0] = fmaf(qv.w, kv.x, acc[3][0]);
                acc[3][1] = fmaf(qv.w, kv.y, acc[3][1]);
                acc[3][2] = fmaf(qv.w, kv.z, acc[3][2]);
                acc[3][3] = fmaf(qv.w, kv.w, acc[3][3]);
            }

#pragma unroll
            for (int i = 0; i < 4; i++) {
                const int q = (qi << 2) + i;
                const float4 mk = *(const float4*)&mask[(size_t)(q0 + q) * S + c * TK + (ki << 2)];
                float4 o;
                o.x = fmaf(acc[i][0], SCALE, mk.x);
                o.y = fmaf(acc[i][1], SCALE, mk.y);
                o.z = fmaf(acc[i][2], SCALE, mk.z);
                o.w = fmaf(acc[i][3], SCALE, mk.w);
                *(float4*)&Ss[q * SROW + c * TK + (ki << 2)] = o;
                rmax[i] = fmaxf(rmax[i], fmaxf(fmaxf(o.x, o.y), fmaxf(o.z, o.w)));
            }
        }

        // ---- row-max reduce ----
#pragma unroll
        for (int j = 0; j < 4; j++) {
            float m = rmax[j];
#pragma unroll
            for (int o = 16; o; o >>= 1) m = fmaxf(m, __shfl_xor_sync(0xFFFFFFFFu, m, o));
            rmax[j] = m;
        }
        if (lane == 0) {
#pragma unroll
            for (int j = 0; j < 4; j++) Rb[qi * 8 + (w & 1) * 4 + j] = rmax[j];
        }
        __syncthreads();

        // stage V chunk 0; prefetch V chunk 1
#pragma unroll
        for (int i = 0; i < 8; i++) {
            int p4 = t + (i << 8);
            *(float4*)&KVs[(p4 >> 4) * DK + ((p4 & 15) << 2)] = pf[i];
        }
#pragma unroll
        for (int i = 0; i < 8; i++) {
            int p4 = t + (i << 8);
            pf[i] = *(const float4*)&Vg[(size_t)(VCH + (p4 >> 4)) * DK + ((p4 & 15) << 2)];
        }

        // ---- softmax + batched attn RMW (float4 vectorized) ----
#pragma unroll
        for (int rr = 0; rr < 2; rr++) {
            const int q = w * 2 + rr;
            float* row = Ss + q * SROW;
            const float m = fmaxf(Rb[(q >> 2) * 8 + (q & 3)],
                                  Rb[(q >> 2) * 8 + 4 + (q & 3)]);
            float l0 = 0.f, l1 = 0.f, l2 = 0.f, l3 = 0.f;
            for (int i = lane * 4; i < S; i += 128) {
                float4 e = *(float4*)&row[i];
                e.x = __expf(e.x - m); e.y = __expf(e.y - m);
                e.z = __expf(e.z - m); e.w = __expf(e.w - m);
                *(float4*)&row[i] = e;                 // raw exp stays in smem
                l0 += e.x; l1 += e.y; l2 += e.z; l3 += e.w;
            }
            float l = (l0 + l1) + (l2 + l3);
#pragma unroll
            for (int o = 16; o; o >>= 1) l += __shfl_xor_sync(0xFFFFFFFFu, l, o);
            const float inv = 1.f / l;
            if (lane == 0) Lb[q] = inv;
            const float invk = inv * 0.125f;

            float* __restrict__ arow = attn_dst + ((size_t)b * S + q0 + q) * S;
            for (int i = lane * 4; i < S; i += 128) {
                float4 e = *(float4*)&row[i];
                float4 a;
                a.x = e.x * invk; a.y = e.y * invk;
                a.z = e.z * invk; a.w = e.w * invk;
                if (hh > 0) {
                    float4 prev = *(float4*)&arow[i];
                    a.x += prev.x; a.y += prev.y; a.z += prev.z; a.w += prev.w;
                }
                *(float4*)&arow[i] = a;
            }
        }
        __syncthreads();                   // V buf0 + Lb + exp values visible

        // ================= PV: 16 chunks of 128 rows, double-buffered =======
        float4 cacc[4];
#pragma unroll
        for (int i = 0; i < 4; i++) cacc[i] = make_float4(0.f, 0.f, 0.f, 0.f);

        const int rb = qi << 5;
        for (int c = 0; c < NVC; c++) {
            const float* buf = KVs + (c & 1) * 8192;
            if (c < NVC - 1) {
                float* nbuf = KVs + ((c + 1) & 1) * 8192;
#pragma unroll
                for (int i = 0; i < 8; i++) {
                    int p4 = t + (i << 8);
                    *(float4*)&nbuf[(p4 >> 4) * DK + ((p4 & 15) << 2)] = pf[i];
                }
            }
            if (c < NVC - 2) {
#pragma unroll
                for (int i = 0; i < 8; i++) {
                    int p4 = t + (i << 8);
                    pf[i] = *(const float4*)&Vg[(size_t)((c + 2) * VCH + (p4 >> 4)) * DK + ((p4 & 15) << 2)];
                }
            }
#pragma unroll
            for (int kk = 0; kk < 32; kk += 4) {
                const float4 v0 = *(const float4*)&buf[(rb + kk + 0) * DK + cg4];
                const float4 v1 = *(const float4*)&buf[(rb + kk + 1) * DK + cg4];
                const float4 v2 = *(const float4*)&buf[(rb + kk + 2) * DK + cg4];
                const float4 v3 = *(const float4*)&buf[(rb + kk + 3) * DK + cg4];
#pragma unroll
                for (int i = 0; i < 4; i++) {
                    const float4 p = *(const float4*)&Ss[(qg4 + i) * SROW + c * VCH + rb + kk];
                    cacc[i].x = fmaf(p.x, v0.x, cacc[i].x);
                    cacc[i].y = fmaf(p.x, v0.y, cacc[i].y);
                    cacc[i].z = fmaf(p.x, v0.z, cacc[i].z);
                    cacc[i].w = fmaf(p.x, v0.w, cacc[i].w);
                    cacc[i].x = fmaf(p.y, v1.x, cacc[i].x);
                    cacc[i].y = fmaf(p.y, v1.y, cacc[i].y);
                    cacc[i].z = fmaf(p.y, v1.z, cacc[i].z);
                    cacc[i].w = fmaf(p.y, v1.w, cacc[i].w);
                    cacc[i].x = fmaf(p.z, v2.x, cacc[i].x);
                    cacc[i].y = fmaf(p.z, v2.y, cacc[i].y);
                    cacc[i].z = fmaf(p.z, v2.z, cacc[i].z);
                    cacc[i].w = fmaf(p.z, v2.w, cacc[i].w);
                    cacc[i].x = fmaf(p.w, v3.x, cacc[i].x);
                    cacc[i].y = fmaf(p.w, v3.y, cacc[i].y);
                    cacc[i].z = fmaf(p.w, v3.z, cacc[i].z);
                    cacc[i].w = fmaf(p.w, v3.w, cacc[i].w);
                }
            }
            __syncthreads();
        }

        // ---- deferred normalization + partial reduce ----
#pragma unroll
        for (int i = 0; i < 4; i++) {
            const float f = Lb[qg4 + i];
            cacc[i].x *= f; cacc[i].y *= f; cacc[i].z *= f; cacc[i].w *= f;
        }
#pragma unroll
        for (int i = 0; i < 4; i++)
            *(float4*)&KVs[(qi << 10) + (qg4 + i) * DK + cg4] = cacc[i];
        __syncthreads();
        {
            const int q  = t >> 4;
            const int c4 = (t & 15) << 2;
            float4 s0 = *(const float4*)&KVs[0 * 1024 + q * DK + c4];
            float4 s1 = *(const float4*)&KVs[1 * 1024 + q * DK + c4];
            float4 s2 = *(const float4*)&KVs[2 * 1024 + q * DK + c4];
            float4 s3 = *(const float4*)&KVs[3 * 1024 + q * DK + c4];
            float4 o;
            o.x = (s0.x + s1.x) + (s2.x + s3.x);
            o.y = (s0.y + s1.y) + (s2.y + s3.y);
            o.z = (s0.z + s1.z) + (s2.z + s3.z);
            o.w = (s0.w + s1.w) + (s2.w + s3.w);
            *(float4*)&g_ctx[((size_t)b * S + q0 + q) * D + h * DK + c4] = o;
        }
    }
}

// ---------------------------------------------------------------------------
// K3: attn_out += g_attn2
// ---------------------------------------------------------------------------
__global__ __launch_bounds__(256) void k3_merge(float* __restrict__ attn_out)
{
    using namespace cfg;
    const size_t i4 = (size_t)blockIdx.x * 256 + threadIdx.x;
    float4 a = ((const float4*)g_attn2)[i4];
    float4 o = ((float4*)attn_out)[i4];
    o.x += a.x; o.y += a.y; o.z += a.z; o.w += a.w;
    ((float4*)attn_out)[i4] = o;
}

// ---------------------------------------------------------------------------
// K5: out = ctx @ Wout. 64x128 tiles, FFMA2 inner.
// ---------------------------------------------------------------------------
__global__ __launch_bounds__(256) void k5_out(
    const float* __restrict__ Wout, float* __restrict__ out)
{
    using namespace cfg;
    constexpr int BM = 64, BN = 128, BK = 16;
    __shared__ float As[BK][BM + 4];
    __shared__ float Bs[BK][BN];

    const int row0 = blockIdx.x * BM;
    const int col0 = blockIdx.y * BN;
    const int t  = threadIdx.x;
    const int tm = (t >> 5) << 3;
    const int tn = (t & 31) << 2;

    unsigned long long acc2[8][2];
#pragma unroll
    for (int i = 0; i < 8; i++) { acc2[i][0] = 0ULL; acc2[i][1] = 0ULL; }

    for (int k0 = 0; k0 < D; k0 += BK) {
#pragma unroll
        for (int i = 0; i < 4; i++) {
            int p = t + i * 256;
            int m = p >> 4, k = p & 15;
            As[k][m] = g_ctx[(size_t)(row0 + m) * D + k0 + k];
        }
#pragma unroll
        for (int i = 0; i < 8; i++) {
            int p = t + i * 256;
            int k = p >> 7, n = p & 127;
            Bs[k][n] = Wout[(size_t)(k0 + k) * D + col0 + n];
        }
        __syncthreads();
#pragma unroll
        for (int k = 0; k < BK; k++) {
            const ulonglong2 bb = *(const ulonglong2*)&Bs[k][tn];
            float a[8];
#pragma unroll
            for (int i = 0; i < 8; i++) a[i] = As[k][tm + i];
#pragma unroll
            for (int i = 0; i < 8; i++) {
                const unsigned long long aa = pack2(a[i]);
                ffma2(acc2[i][0], aa, bb.x);
                ffma2(acc2[i][1], aa, bb.y);
            }
        }
        __syncthreads();
    }
#pragma unroll
    for (int i = 0; i < 8; i++) {
        const int r = row0 + tm + i;
        const float2 v0 = unpack2(acc2[i][0]);
        const float2 v1 = unpack2(acc2[i][1]);
        *(float4*)&out[(size_t)r * D + col0 + tn] =
            make_float4(v0.x, v0.y, v1.x, v1.y);
    }
}

// ---------------------------------------------------------------------------
namespace {
cudaStream_t g_side = nullptr;
cudaEvent_t  g_evFork = nullptr, g_evJoin = nullptr;
struct CudaWarm {
    CudaWarm() {
        cudaFuncSetAttribute(k2_attn,
            cudaFuncAttributeMaxDynamicSharedMemorySize, cfg::SMEM2);
        cudaStreamCreateWithFlags(&g_side, cudaStreamNonBlocking);
        cudaEventCreateWithFlags(&g_evFork, cudaEventDisableTiming);
        cudaEventCreateWithFlags(&g_evJoin, cudaEventDisableTiming);
        cudaFuncAttributes a;
        cudaFuncGetAttributes(&a, (const void*)k1_qkv);
        cudaFuncGetAttributes(&a, (const void*)k2_attn);
        cudaFuncGetAttributes(&a, (const void*)k3_merge);
        cudaFuncGetAttributes(&a, (const void*)k5_out);
    }
};
CudaWarm g_warm;
}

// ---------------------------------------------------------------------------
extern "C" void kernel_launch(void* const* d_in, const int* in_sizes, int n_in,
                              void* d_out, int out_size)
{
    using namespace cfg;
    const float* Zq   = (const float*)d_in[0];
    const float* Zkv  = (const float*)d_in[1];
    const float* mask = (const float*)d_in[2];
    const float* Wqkv = (const float*)d_in[3];
    const float* Wout = (const float*)d_in[4];

    float* out       = (float*)d_out;
    float* attn_mean = out + (size_t)B * S * D;

    cudaFuncSetAttribute(k2_attn,
        cudaFuncAttributeMaxDynamicSharedMemorySize, SMEM2);

    k1_qkv<<<dim3(MROWS / 128, N3 / 128), 256>>>(Zq, Zkv, Wqkv);
    k2_attn<<<dim3(S / TQ, B, 2), 256, SMEM2>>>(mask, attn_mean);

    const int mergeBlocks = (int)((size_t)B * S * S / 4 / 256);
    if (g_side && g_evFork && g_evJoin) {
        cudaEventRecord(g_evFork, 0);
        cudaStreamWaitEvent(g_side, g_evFork, 0);
        k3_merge<<<mergeBlocks, 256, 0, g_side>>>(attn_mean);
        k5_out<<<dim3(MROWS / 64, D / 128), 256>>>(Wout, out);
        cudaEventRecord(g_evJoin, g_side);
        cudaStreamWaitEvent(0, g_evJoin, 0);
    } else {
        k3_merge<<<mergeBlocks, 256>>>(attn_mean);
        k5_out<<<dim3(MROWS / 64, D / 128), 256>>>(Wout, out);
    }
}